// round 8
// baseline (speedup 1.0000x reference)
#include <cuda_runtime.h>
#include <cuda_bf16.h>
#include <cstdint>

#define VOCAB 10000
#define EMB   100
#define SEQ   80
#define BATCH 1024
#define UNITS 512
#define ZDIM  2048            // 4*UNITS
#define K1    512             // layer1 K (pure bf16)
#define K2    1024            // layer2 K ([h1|h2])
#define NCTAS 128             // 16 x 8 grid, all co-resident (< 148 SMs)

// ---------------- device scratch (static, no allocations) ----------------
__device__ float         g_EmbW1[(size_t)VOCAB * ZDIM];       // emb@W1+b1 fp32 (82MB)
__device__ __nv_bfloat16 g_B1[(size_t)ZDIM * K1];             // [n][k]  U1^T  bf16
__device__ __nv_bfloat16 g_B2[(size_t)ZDIM * K2];             // [n][k]  [W2;U2]^T bf16
__device__ __nv_bfloat16 g_A1[2][(size_t)BATCH * K1];         // h1 bf16, ping-pong
__device__ __nv_bfloat16 g_A2[2][(size_t)BATCH * K2];         // [h1 | h2] bf16, ping-pong
__device__ float         g_H2f[(size_t)BATCH * UNITS];        // fp32 h2 for output head
__device__ float         g_C1[(size_t)BATCH * UNITS];
__device__ float         g_C2[(size_t)BATCH * UNITS];
__device__ unsigned      g_bar;                               // grid barrier counter

// ---------------- helpers ----------------
__device__ __forceinline__ uint32_t smem_u32(const void* p) {
    uint32_t a;
    asm("{ .reg .u64 t; cvta.to.shared.u64 t, %1; cvt.u32.u64 %0, t; }" : "=r"(a) : "l"(p));
    return a;
}
__device__ __forceinline__ void cp16(uint32_t sa, const void* g) {
    asm volatile("cp.async.cg.shared.global [%0], [%1], 16;" :: "r"(sa), "l"(g));
}
#define CP_COMMIT() asm volatile("cp.async.commit_group;")

__device__ __forceinline__ void ldmA(uint32_t a, uint32_t* r) {
    asm volatile("ldmatrix.sync.aligned.m8n8.x4.shared.b16 {%0,%1,%2,%3}, [%4];"
                 : "=r"(r[0]), "=r"(r[1]), "=r"(r[2]), "=r"(r[3]) : "r"(a));
}
// B stored [n][k]: NO trans (verified R5/R6).
__device__ __forceinline__ void ldmB(uint32_t a, uint32_t* r) {
    asm volatile("ldmatrix.sync.aligned.m8n8.x2.shared.b16 {%0,%1}, [%2];"
                 : "=r"(r[0]), "=r"(r[1]) : "r"(a));
}
__device__ __forceinline__ void mma16816(float* c, const uint32_t* a, const uint32_t* b) {
    asm volatile("mma.sync.aligned.m16n8k16.row.col.f32.bf16.bf16.f32 "
                 "{%0,%1,%2,%3},{%4,%5,%6,%7},{%8,%9},{%0,%1,%2,%3};"
                 : "+f"(c[0]), "+f"(c[1]), "+f"(c[2]), "+f"(c[3])
                 : "r"(a[0]), "r"(a[1]), "r"(a[2]), "r"(a[3]), "r"(b[0]), "r"(b[1]));
}
__device__ __forceinline__ float sigm(float x) { return __fdividef(1.0f, 1.0f + __expf(-x)); }

// ---------------- init / prep ----------------
__global__ void zero_state() {
    size_t i = (size_t)blockIdx.x * blockDim.x + threadIdx.x;
    size_t stride = (size_t)gridDim.x * blockDim.x;
    if (i == 0) g_bar = 0u;   // reset grid barrier every launch (graph replay safe)
    for (size_t k = i; k < (size_t)BATCH * K1; k += stride) { g_A1[0][k] = __nv_bfloat16(0.f); g_A1[1][k] = __nv_bfloat16(0.f); }
    for (size_t k = i; k < (size_t)BATCH * K2; k += stride) { g_A2[0][k] = __nv_bfloat16(0.f); g_A2[1][k] = __nv_bfloat16(0.f); }
    for (size_t k = i; k < (size_t)BATCH * UNITS; k += stride) { g_C1[k] = 0.f; g_C2[k] = 0.f; }
}

__global__ void make_B1(const float* __restrict__ U1) {
    size_t i = (size_t)blockIdx.x * blockDim.x + threadIdx.x;
    if (i >= (size_t)ZDIM * K1) return;
    int n = (int)(i / K1), k = (int)(i % K1);
    g_B1[i] = __float2bfloat16(U1[k * ZDIM + n]);
}

__global__ void make_B2(const float* __restrict__ W2, const float* __restrict__ U2) {
    size_t i = (size_t)blockIdx.x * blockDim.x + threadIdx.x;
    if (i >= (size_t)ZDIM * K2) return;
    int n = (int)(i / K2), k = (int)(i % K2);
    float w = (k < 512) ? W2[k * ZDIM + n] : U2[(k - 512) * ZDIM + n];
    g_B2[i] = __float2bfloat16(w);
}

// EmbW1[v][c] = sum_e emb[v][e]*W1[e][c] + b1[c]  (fp32)
__global__ __launch_bounds__(256) void embw1_kernel(const float* __restrict__ emb,
                                                    const float* __restrict__ W1,
                                                    const float* __restrict__ b1) {
    __shared__ float Ae[32][65];
    __shared__ float Be[32][64];
    int tid = threadIdx.x;
    int tx = tid & 15, ty = tid >> 4;
    int vBase = blockIdx.y * 64, cBase = blockIdx.x * 64;
    float acc[4][4];
#pragma unroll
    for (int i = 0; i < 4; ++i)
#pragma unroll
        for (int j = 0; j < 4; ++j) acc[i][j] = 0.0f;
    for (int kt = 0; kt < 4; ++kt) {
        {
            int vrow = tid >> 2, k0 = (tid & 3) * 8;
            int v = vBase + vrow;
#pragma unroll
            for (int j = 0; j < 8; ++j) {
                int k = kt * 32 + k0 + j;
                Ae[k0 + j][vrow] = (k < EMB && v < VOCAB) ? emb[v * EMB + k] : 0.0f;
            }
        }
        {
            int krow = tid >> 3, c0 = (tid & 7) * 8;
            int k = kt * 32 + krow;
#pragma unroll
            for (int j = 0; j < 8; ++j)
                Be[krow][c0 + j] = (k < EMB) ? W1[k * ZDIM + cBase + c0 + j] : 0.0f;
        }
        __syncthreads();
#pragma unroll
        for (int kk = 0; kk < 32; ++kk) {
            float a[4], b[4];
#pragma unroll
            for (int i = 0; i < 4; ++i) a[i] = Ae[kk][ty * 4 + i];
#pragma unroll
            for (int j = 0; j < 4; ++j) b[j] = Be[kk][tx * 4 + j];
#pragma unroll
            for (int i = 0; i < 4; ++i)
#pragma unroll
                for (int j = 0; j < 4; ++j) acc[i][j] = fmaf(a[i], b[j], acc[i][j]);
        }
        __syncthreads();
    }
#pragma unroll
    for (int i = 0; i < 4; ++i) {
        int v = vBase + ty * 4 + i;
        if (v >= VOCAB) continue;
#pragma unroll
        for (int j = 0; j < 4; ++j) {
            int c = cBase + tx * 4 + j;
            g_EmbW1[(size_t)v * ZDIM + c] = acc[i][j] + b1[c];
        }
    }
}

// ---------------- persistent LSTM kernel ----------------
#define ROWB 80

// one GEMM+cell step for one layer (structure identical to verified R6 kernel)
template<int KP, int LAYER>
__device__ __forceinline__ void step_body(
    const int* __restrict__ tokens, const float* __restrict__ b2, int t,
    const __nv_bfloat16* __restrict__ Ag, const __nv_bfloat16* __restrict__ Bg,
    float* __restrict__ Cst, __nv_bfloat16* __restrict__ d1, __nv_bfloat16* __restrict__ d2,
    int rowTile, int uTile,
    uint32_t sA0, uint32_t sA1, uint32_t sB0, uint32_t sB1,
    const int* l_r, const int* l_c, const uint32_t* l_so,
    int a_row, int a_c16, int b_row, int b_c16, int u0,
    int tid, int warp_m, int lane)
{
    const size_t strideBy = (size_t)KP * 2;
    const char* Agc = (const char*)Ag;
    const char* Bgc = (const char*)Bg;

    size_t l_aoff[4], l_boff[4];
#pragma unroll
    for (int i = 0; i < 4; ++i) {
        l_aoff[i] = (size_t)(rowTile + l_r[i]) * strideBy + l_c[i] * 16;
        int n = ((l_r[i] >> 5) * 512) + uTile + (l_r[i] & 31);
        l_boff[i] = (size_t)n * strideBy + l_c[i] * 16;
    }

    float acc[4][4][4];
#pragma unroll
    for (int mi = 0; mi < 4; ++mi)
#pragma unroll
        for (int g = 0; g < 4; ++g)
#pragma unroll
            for (int j = 0; j < 4; ++j) acc[mi][g][j] = 0.0f;

    const int NT = KP >> 5;

    // preload tile 0
#pragma unroll
    for (int i = 0; i < 4; ++i) {
        int id = i * 256 + tid;
        if (id < 512) cp16(sA0 + l_so[i], Agc + l_aoff[i]);
        else          cp16(sB0 + l_so[i], Bgc + l_boff[i]);
    }
    CP_COMMIT();

    for (int kt = 0; kt < NT; ++kt) {
        int b = kt & 1;
        uint32_t sA = b ? sA1 : sA0;
        uint32_t sB = b ? sB1 : sB0;
        if (kt + 1 < NT) {
            uint32_t dA = b ? sA0 : sA1;
            uint32_t dB = b ? sB0 : sB1;
            size_t go = (size_t)(kt + 1) * 64;
#pragma unroll
            for (int i = 0; i < 4; ++i) {
                int id = i * 256 + tid;
                if (id < 512) cp16(dA + l_so[i], Agc + l_aoff[i] + go);
                else          cp16(dB + l_so[i], Bgc + l_boff[i] + go);
            }
            CP_COMMIT();
            asm volatile("cp.async.wait_group 1;");
        } else {
            asm volatile("cp.async.wait_group 0;");
        }
        __syncthreads();

#pragma unroll
        for (int ks = 0; ks < 2; ++ks) {
            uint32_t af[4][4], bf[4][2];
#pragma unroll
            for (int mi = 0; mi < 4; ++mi)
                ldmA(sA + (uint32_t)((a_row + mi * 16) * ROWB + ks * 32 + a_c16 * 16), af[mi]);
#pragma unroll
            for (int g = 0; g < 4; ++g)
                ldmB(sB + (uint32_t)((b_row + g * 32) * ROWB + ks * 32 + b_c16 * 16), bf[g]);
#pragma unroll
            for (int mi = 0; mi < 4; ++mi)
#pragma unroll
                for (int g = 0; g < 4; ++g)
                    mma16816(acc[mi][g], af[mi], bf[g]);
        }
        __syncthreads();
    }

    // epilogue (thread-local gates; layout verified in R5/R6)
#pragma unroll
    for (int mi = 0; mi < 4; ++mi) {
#pragma unroll
        for (int h = 0; h < 2; ++h) {
            int row = rowTile + warp_m * 64 + mi * 16 + (lane >> 2) + h * 8;
            const float* Xrow;
            if (LAYER == 0) Xrow = g_EmbW1 + (size_t)tokens[row * SEQ + t] * ZDIM;
            else            Xrow = b2;
            float2 xz[4];
#pragma unroll
            for (int g = 0; g < 4; ++g) xz[g] = *(const float2*)(Xrow + g * 512 + u0);

            float zi0 = acc[mi][0][h * 2 + 0] + xz[0].x, zi1 = acc[mi][0][h * 2 + 1] + xz[0].y;
            float zf0 = acc[mi][1][h * 2 + 0] + xz[1].x, zf1 = acc[mi][1][h * 2 + 1] + xz[1].y;
            float zg0 = acc[mi][2][h * 2 + 0] + xz[2].x, zg1 = acc[mi][2][h * 2 + 1] + xz[2].y;
            float zo0 = acc[mi][3][h * 2 + 0] + xz[3].x, zo1 = acc[mi][3][h * 2 + 1] + xz[3].y;

            float* cp = Cst + (size_t)row * UNITS + u0;
            float2 c = *(float2*)cp;
            c.x = sigm(zf0) * c.x + sigm(zi0) * tanhf(zg0);
            c.y = sigm(zf1) * c.y + sigm(zi1) * tanhf(zg1);
            *(float2*)cp = c;
            float hv0 = sigm(zo0) * tanhf(c.x);
            float hv1 = sigm(zo1) * tanhf(c.y);

            __nv_bfloat16 bh0 = __float2bfloat16(hv0);
            __nv_bfloat16 bh1 = __float2bfloat16(hv1);
            uint32_t hiP = ((uint32_t)*(unsigned short*)&bh1 << 16) | *(unsigned short*)&bh0;

            if (LAYER == 0) {
                *(uint32_t*)(d1 + (size_t)row * K1 + u0) = hiP;          // h1 -> A1[other]
                *(uint32_t*)(d2 + (size_t)row * K2 + u0) = hiP;          // h1 -> A2[cur] h1-part
            } else {
                *(uint32_t*)(d1 + (size_t)row * K2 + 512 + u0) = hiP;    // h2 -> A2[other] h2-part
                *(float2*)(g_H2f + (size_t)row * UNITS + u0) = make_float2(hv0, hv1);
            }
        }
    }
}

__device__ __forceinline__ void grid_barrier(unsigned& gen) {
    __syncthreads();
    gen += NCTAS;
    if (threadIdx.x == 0) {
        __threadfence();
        atomicAdd(&g_bar, 1u);
        while (*(volatile unsigned*)&g_bar < gen) { }
        __threadfence();
    }
    __syncthreads();
}

__global__ __launch_bounds__(256) void lstm_persist(const int* __restrict__ tokens,
                                                    const float* __restrict__ b2) {
    __shared__ __align__(128) char smA[2][128 * ROWB];
    __shared__ __align__(128) char smB[2][128 * ROWB];

    const int tid = threadIdx.x;
    const int wid = tid >> 5, lane = tid & 31;
    const int warp_m = wid >> 2, warp_n = wid & 3;
    const int rowTile = blockIdx.y * 128;
    const int uTile = blockIdx.x * 32;

    const uint32_t sA0 = smem_u32(smA[0]), sA1 = smem_u32(smA[1]);
    const uint32_t sB0 = smem_u32(smB[0]), sB1 = smem_u32(smB[1]);

    // loader lane constants (hoisted out of the time loop)
    int l_r[4], l_c[4];
    uint32_t l_so[4];
#pragma unroll
    for (int i = 0; i < 4; ++i) {
        int id = i * 256 + tid;
        int idx = id & 511;
        l_r[i] = idx >> 2; l_c[i] = idx & 3;
        l_so[i] = (uint32_t)(l_r[i] * ROWB + l_c[i] * 16);
    }
    const int a_row = warp_m * 64 + (lane & 7) + ((lane >> 3) & 1) * 8;
    const int a_c16 = (lane >> 4) & 1;
    const int l15 = lane & 15;
    const int b_row = warp_n * 8 + (l15 & 7);
    const int b_c16 = l15 >> 3;
    const int u0 = uTile + warp_n * 8 + (lane & 3) * 2;

    unsigned gen = 0;

    for (int t = 0; t < SEQ; ++t) {
        const int s = t & 1;
        step_body<K1, 0>(tokens, b2, t, g_A1[s], g_B1, g_C1,
                         g_A1[s ^ 1], g_A2[s], rowTile, uTile,
                         sA0, sA1, sB0, sB1, l_r, l_c, l_so,
                         a_row, a_c16, b_row, b_c16, u0, tid, warp_m, lane);
        grid_barrier(gen);
        step_body<K2, 1>(tokens, b2, t, g_A2[s], g_B2, g_C2,
                         g_A2[s ^ 1], nullptr, rowTile, uTile,
                         sA0, sA1, sB0, sB1, l_r, l_c, l_so,
                         a_row, a_c16, b_row, b_c16, u0, tid, warp_m, lane);
        grid_barrier(gen);
    }
}

// ---------------- output head ----------------
__global__ void out_kernel(const float* __restrict__ Wout, const float* __restrict__ bout,
                           float* __restrict__ out) {
    int row = (blockIdx.x * blockDim.x + threadIdx.x) >> 5;
    int lane = threadIdx.x & 31;
    float s = 0.0f;
    for (int k = lane; k < UNITS; k += 32)
        s += g_H2f[(size_t)row * UNITS + k] * Wout[k];
#pragma unroll
    for (int off = 16; off; off >>= 1) s += __shfl_down_sync(0xffffffffu, s, off);
    if (lane == 0) out[row] = sigm(s + bout[0]);
}

// ---------------- launch ----------------
extern "C" void kernel_launch(void* const* d_in, const int* in_sizes, int n_in,
                              void* d_out, int out_size) {
    const int*   tokens = (const int*)d_in[0];
    const float* emb    = (const float*)d_in[1];
    const float* W1     = (const float*)d_in[2];
    const float* U1     = (const float*)d_in[3];
    const float* b1     = (const float*)d_in[4];
    const float* W2     = (const float*)d_in[5];
    const float* U2     = (const float*)d_in[6];
    const float* b2     = (const float*)d_in[7];
    const float* Wout   = (const float*)d_in[8];
    const float* bout   = (const float*)d_in[9];
    float* out = (float*)d_out;

    zero_state<<<1024, 256>>>();
    make_B1<<<((size_t)ZDIM * K1 + 255) / 256, 256>>>(U1);
    make_B2<<<((size_t)ZDIM * K2 + 255) / 256, 256>>>(W2, U2);
    embw1_kernel<<<dim3(ZDIM / 64, (VOCAB + 63) / 64), 256>>>(emb, W1, b1);

    lstm_persist<<<dim3(16, 8), 256>>>(tokens, b2);   // 128 CTAs, all co-resident

    out_kernel<<<BATCH / 8, 256>>>(Wout, bout, out);
}

// round 11
// speedup vs baseline: 1.0020x; 1.0020x over previous
#include <cuda_runtime.h>
#include <cuda_bf16.h>
#include <cstdint>

#define VOCAB 10000
#define EMB   100
#define SEQ   80
#define BATCH 1024
#define UNITS 512
#define ZDIM  2048            // 4*UNITS
#define K1    512             // layer1 K (pure bf16)
#define K2    1024            // layer2 K ([h1|h2])

// ---------------- device scratch (static, no allocations) ----------------
__device__ float         g_EmbW1[(size_t)VOCAB * ZDIM];       // emb@W1+b1 fp32 (82MB)
__device__ __nv_bfloat16 g_B1[(size_t)ZDIM * K1];             // [n][k]  U1^T  bf16
__device__ __nv_bfloat16 g_B2[(size_t)ZDIM * K2];             // [n][k]  [W2;U2]^T bf16
__device__ __nv_bfloat16 g_A1[2][(size_t)BATCH * K1];         // h1 bf16, ping-pong
__device__ __nv_bfloat16 g_A2[2][(size_t)BATCH * K2];         // [h1 | h2] bf16, ping-pong
__device__ float         g_H2f[(size_t)BATCH * UNITS];        // fp32 h2 for output head
__device__ float         g_C1[(size_t)BATCH * UNITS];
__device__ float         g_C2[(size_t)BATCH * UNITS];

// ---------------- helpers ----------------
__device__ __forceinline__ uint32_t smem_u32(const void* p) {
    uint32_t a;
    asm("{ .reg .u64 t; cvta.to.shared.u64 t, %1; cvt.u32.u64 %0, t; }" : "=r"(a) : "l"(p));
    return a;
}
__device__ __forceinline__ void cp16(uint32_t sa, const void* g) {
    asm volatile("cp.async.cg.shared.global [%0], [%1], 16;" :: "r"(sa), "l"(g));
}
#define CP_COMMIT() asm volatile("cp.async.commit_group;")

__device__ __forceinline__ void ldmA(uint32_t a, uint32_t* r) {
    asm volatile("ldmatrix.sync.aligned.m8n8.x4.shared.b16 {%0,%1,%2,%3}, [%4];"
                 : "=r"(r[0]), "=r"(r[1]), "=r"(r[2]), "=r"(r[3]) : "r"(a));
}
// B stored [n][k]: NO trans (verified R5/R6).
__device__ __forceinline__ void ldmB(uint32_t a, uint32_t* r) {
    asm volatile("ldmatrix.sync.aligned.m8n8.x2.shared.b16 {%0,%1}, [%2];"
                 : "=r"(r[0]), "=r"(r[1]) : "r"(a));
}
__device__ __forceinline__ void mma16816(float* c, const uint32_t* a, const uint32_t* b) {
    asm volatile("mma.sync.aligned.m16n8k16.row.col.f32.bf16.bf16.f32 "
                 "{%0,%1,%2,%3},{%4,%5,%6,%7},{%8,%9},{%0,%1,%2,%3};"
                 : "+f"(c[0]), "+f"(c[1]), "+f"(c[2]), "+f"(c[3])
                 : "r"(a[0]), "r"(a[1]), "r"(a[2]), "r"(a[3]), "r"(b[0]), "r"(b[1]));
}
__device__ __forceinline__ float sigm(float x) { return __fdividef(1.0f, 1.0f + __expf(-x)); }

// ---------------- init / prep ----------------
__global__ void zero_state() {
    size_t i = (size_t)blockIdx.x * blockDim.x + threadIdx.x;
    size_t stride = (size_t)gridDim.x * blockDim.x;
    for (size_t k = i; k < (size_t)BATCH * K1; k += stride) { g_A1[0][k] = __nv_bfloat16(0.f); g_A1[1][k] = __nv_bfloat16(0.f); }
    for (size_t k = i; k < (size_t)BATCH * K2; k += stride) { g_A2[0][k] = __nv_bfloat16(0.f); g_A2[1][k] = __nv_bfloat16(0.f); }
    for (size_t k = i; k < (size_t)BATCH * UNITS; k += stride) { g_C1[k] = 0.f; g_C2[k] = 0.f; }
}

__global__ void make_B1(const float* __restrict__ U1) {
    size_t i = (size_t)blockIdx.x * blockDim.x + threadIdx.x;
    if (i >= (size_t)ZDIM * K1) return;
    int n = (int)(i / K1), k = (int)(i % K1);
    g_B1[i] = __float2bfloat16(U1[k * ZDIM + n]);
}

__global__ void make_B2(const float* __restrict__ W2, const float* __restrict__ U2) {
    size_t i = (size_t)blockIdx.x * blockDim.x + threadIdx.x;
    if (i >= (size_t)ZDIM * K2) return;
    int n = (int)(i / K2), k = (int)(i % K2);
    float w = (k < 512) ? W2[k * ZDIM + n] : U2[(k - 512) * ZDIM + n];
    g_B2[i] = __float2bfloat16(w);
}

// EmbW1[v][c] = sum_e emb[v][e]*W1[e][c] + b1[c]  (fp32)
// Vectorized smem reads: float4 (Ae pad 68 words -> 16B-aligned rows).
__global__ __launch_bounds__(256) void embw1_kernel(const float* __restrict__ emb,
                                                    const float* __restrict__ W1,
                                                    const float* __restrict__ b1) {
    __shared__ __align__(16) float Ae[32][68];
    __shared__ __align__(16) float Be[32][64];
    int tid = threadIdx.x;
    int tx = tid & 15, ty = tid >> 4;
    int vBase = blockIdx.y * 64, cBase = blockIdx.x * 64;
    float acc[4][4];
#pragma unroll
    for (int i = 0; i < 4; ++i)
#pragma unroll
        for (int j = 0; j < 4; ++j) acc[i][j] = 0.0f;
    for (int kt = 0; kt < 4; ++kt) {
        {
            int vrow = tid >> 2, k0 = (tid & 3) * 8;
            int v = vBase + vrow;
#pragma unroll
            for (int j = 0; j < 8; ++j) {
                int k = kt * 32 + k0 + j;
                Ae[k0 + j][vrow] = (k < EMB && v < VOCAB) ? emb[v * EMB + k] : 0.0f;
            }
        }
        {
            int krow = tid >> 3, c0 = (tid & 7) * 8;
            int k = kt * 32 + krow;
#pragma unroll
            for (int j = 0; j < 8; ++j)
                Be[krow][c0 + j] = (k < EMB) ? W1[k * ZDIM + cBase + c0 + j] : 0.0f;
        }
        __syncthreads();
#pragma unroll
        for (int kk = 0; kk < 32; ++kk) {
            float4 a4 = *(const float4*)&Ae[kk][ty * 4];
            float4 b4 = *(const float4*)&Be[kk][tx * 4];
            float a[4] = {a4.x, a4.y, a4.z, a4.w};
            float b[4] = {b4.x, b4.y, b4.z, b4.w};
#pragma unroll
            for (int i = 0; i < 4; ++i)
#pragma unroll
                for (int j = 0; j < 4; ++j) acc[i][j] = fmaf(a[i], b[j], acc[i][j]);
        }
        __syncthreads();
    }
#pragma unroll
    for (int i = 0; i < 4; ++i) {
        int v = vBase + ty * 4 + i;
        if (v >= VOCAB) continue;
#pragma unroll
        for (int j = 0; j < 4; ++j) {
            int c = cBase + tx * 4 + j;
            g_EmbW1[(size_t)v * ZDIM + c] = acc[i][j] + b1[c];
        }
    }
}

// ---------------- HMMA step kernel ----------------
// BM=64 (2 CTAs/SM for prologue/epilogue overlap), BN=128 z-cols (32 units x 4 gates).
// grid (16, 16): blockIdx.x = unit tile, blockIdx.y = batch row tile (64 rows).
// 256 threads = 8 warps (2 warp_m x 4 warp_n). BK=32, double-buffered.
#define ROWB 80

__global__ __launch_bounds__(256, 2) void lstm_tc(const int* __restrict__ tokens,
                                                  const float* __restrict__ b2,
                                                  int t, int q, int p, int layer) {
    __shared__ __align__(128) char smA[2][64 * ROWB];
    __shared__ __align__(128) char smB[2][128 * ROWB];

    const int tid = threadIdx.x;
    const int wid = tid >> 5, lane = tid & 31;
    const int warp_m = wid >> 2, warp_n = wid & 3;

    const __nv_bfloat16 *Ag, *Bg;
    float* Cst;
    int KP;
    if (layer == 0) { Ag = g_A1[q]; Bg = g_B1; KP = K1; Cst = g_C1; }
    else            { Ag = g_A2[p]; Bg = g_B2; KP = K2; Cst = g_C2; }

    const int rowTile = blockIdx.y * 64;
    const int uTile = blockIdx.x * 32;
    const size_t strideBy = (size_t)KP * 2;  // bytes per row of A/B
    const char* Agc = (const char*)Ag;
    const char* Bgc = (const char*)Bg;

    const uint32_t sA0 = smem_u32(smA[0]), sA1 = smem_u32(smA[1]);
    const uint32_t sB0 = smem_u32(smB[0]), sB1 = smem_u32(smB[1]);

    // loaders: A tile 64x32 bf16 = 256 cp16 (1/thread); B tile 128x32 = 512 cp16 (2/thread)
    const int ra = tid >> 2, ca = tid & 3;
    const uint32_t a_so = (uint32_t)(ra * ROWB + ca * 16);
    const size_t a_off = (size_t)(rowTile + ra) * strideBy + ca * 16;
    int b_r[2], b_c[2];
    uint32_t b_so[2];
    size_t b_off[2];
#pragma unroll
    for (int i = 0; i < 2; ++i) {
        int idx = i * 256 + tid;
        b_r[i] = idx >> 2; b_c[i] = idx & 3;
        b_so[i] = (uint32_t)(b_r[i] * ROWB + b_c[i] * 16);
        int n = ((b_r[i] >> 5) * 512) + uTile + (b_r[i] & 31);
        b_off[i] = (size_t)n * strideBy + b_c[i] * 16;
    }

    float acc[2][4][4];
#pragma unroll
    for (int mi = 0; mi < 2; ++mi)
#pragma unroll
        for (int g = 0; g < 4; ++g)
#pragma unroll
            for (int j = 0; j < 4; ++j) acc[mi][g][j] = 0.0f;

    // ldmatrix addresses
    const int a_row = warp_m * 32 + (lane & 7) + ((lane >> 3) & 1) * 8;   // + mi*16
    const int a_c16 = (lane >> 4) & 1;
    const int l15 = lane & 15;
    const int b_row = warp_n * 8 + (l15 & 7);                              // + g*32
    const int b_c16 = l15 >> 3;

    const int NT = KP >> 5;   // 16 (layer1) / 32 (layer2)

    // preload tile 0
    cp16(sA0 + a_so, Agc + a_off);
#pragma unroll
    for (int i = 0; i < 2; ++i) cp16(sB0 + b_so[i], Bgc + b_off[i]);
    CP_COMMIT();

    for (int kt = 0; kt < NT; ++kt) {
        int b = kt & 1;
        uint32_t sA = b ? sA1 : sA0;
        uint32_t sB = b ? sB1 : sB0;
        if (kt + 1 < NT) {
            uint32_t dA = b ? sA0 : sA1;
            uint32_t dB = b ? sB0 : sB1;
            size_t go = (size_t)(kt + 1) * 64;
            cp16(dA + a_so, Agc + a_off + go);
#pragma unroll
            for (int i = 0; i < 2; ++i) cp16(dB + b_so[i], Bgc + b_off[i] + go);
            CP_COMMIT();
            asm volatile("cp.async.wait_group 1;");
        } else {
            asm volatile("cp.async.wait_group 0;");
        }
        __syncthreads();

#pragma unroll
        for (int ks = 0; ks < 2; ++ks) {
            uint32_t af[2][4], bf[4][2];
#pragma unroll
            for (int mi = 0; mi < 2; ++mi)
                ldmA(sA + (uint32_t)((a_row + mi * 16) * ROWB + ks * 32 + a_c16 * 16), af[mi]);
#pragma unroll
            for (int g = 0; g < 4; ++g)
                ldmB(sB + (uint32_t)((b_row + g * 32) * ROWB + ks * 32 + b_c16 * 16), bf[g]);
#pragma unroll
            for (int mi = 0; mi < 2; ++mi)
#pragma unroll
                for (int g = 0; g < 4; ++g)
                    mma16816(acc[mi][g], af[mi], bf[g]);
        }
        __syncthreads();
    }

    // ---------------- epilogue: thread-local gates ----------------
    const int u0 = uTile + warp_n * 8 + (lane & 3) * 2;
    __nv_bfloat16* d1;
    __nv_bfloat16* d2 = nullptr;
    if (layer == 0) { d1 = g_A1[q ^ 1]; d2 = g_A2[p]; }
    else            { d1 = g_A2[p ^ 1]; }

#pragma unroll
    for (int mi = 0; mi < 2; ++mi) {
#pragma unroll
        for (int h = 0; h < 2; ++h) {
            int row = rowTile + warp_m * 32 + mi * 16 + (lane >> 2) + h * 8;
            const float* Xrow;
            if (layer == 0) Xrow = g_EmbW1 + (size_t)tokens[row * SEQ + t] * ZDIM;
            else            Xrow = b2;
            float2 xz[4];
#pragma unroll
            for (int g = 0; g < 4; ++g) xz[g] = *(const float2*)(Xrow + g * 512 + u0);

            float zi0 = acc[mi][0][h * 2 + 0] + xz[0].x, zi1 = acc[mi][0][h * 2 + 1] + xz[0].y;
            float zf0 = acc[mi][1][h * 2 + 0] + xz[1].x, zf1 = acc[mi][1][h * 2 + 1] + xz[1].y;
            float zg0 = acc[mi][2][h * 2 + 0] + xz[2].x, zg1 = acc[mi][2][h * 2 + 1] + xz[2].y;
            float zo0 = acc[mi][3][h * 2 + 0] + xz[3].x, zo1 = acc[mi][3][h * 2 + 1] + xz[3].y;

            float* cp = Cst + (size_t)row * UNITS + u0;
            float2 c = *(float2*)cp;
            c.x = sigm(zf0) * c.x + sigm(zi0) * tanhf(zg0);
            c.y = sigm(zf1) * c.y + sigm(zi1) * tanhf(zg1);
            *(float2*)cp = c;
            float hv0 = sigm(zo0) * tanhf(c.x);
            float hv1 = sigm(zo1) * tanhf(c.y);

            __nv_bfloat16 bh0 = __float2bfloat16(hv0);
            __nv_bfloat16 bh1 = __float2bfloat16(hv1);
            uint32_t hiP = ((uint32_t)*(unsigned short*)&bh1 << 16) | *(unsigned short*)&bh0;

            if (layer == 0) {
                *(uint32_t*)(d1 + (size_t)row * K1 + u0) = hiP;          // h1 -> A1[other]
                *(uint32_t*)(d2 + (size_t)row * K2 + u0) = hiP;          // h1 -> A2[cur] h1-part
            } else {
                *(uint32_t*)(d1 + (size_t)row * K2 + 512 + u0) = hiP;    // h2 -> A2[other] h2-part
                *(float2*)(g_H2f + (size_t)row * UNITS + u0) = make_float2(hv0, hv1);
            }
        }
    }
}

// ---------------- output head ----------------
__global__ void out_kernel(const float* __restrict__ Wout, const float* __restrict__ bout,
                           float* __restrict__ out) {
    int row = (blockIdx.x * blockDim.x + threadIdx.x) >> 5;
    int lane = threadIdx.x & 31;
    float s = 0.0f;
    for (int k = lane; k < UNITS; k += 32)
        s += g_H2f[(size_t)row * UNITS + k] * Wout[k];
#pragma unroll
    for (int off = 16; off; off >>= 1) s += __shfl_down_sync(0xffffffffu, s, off);
    if (lane == 0) out[row] = sigm(s + bout[0]);
}

// ---------------- launch ----------------
extern "C" void kernel_launch(void* const* d_in, const int* in_sizes, int n_in,
                              void* d_out, int out_size) {
    const int*   tokens = (const int*)d_in[0];
    const float* emb    = (const float*)d_in[1];
    const float* W1     = (const float*)d_in[2];
    const float* U1     = (const float*)d_in[3];
    const float* b1     = (const float*)d_in[4];
    const float* W2     = (const float*)d_in[5];
    const float* U2     = (const float*)d_in[6];
    const float* b2     = (const float*)d_in[7];
    const float* Wout   = (const float*)d_in[8];
    const float* bout   = (const float*)d_in[9];
    float* out = (float*)d_out;

    zero_state<<<1024, 256>>>();
    make_B1<<<((size_t)ZDIM * K1 + 255) / 256, 256>>>(U1);
    make_B2<<<((size_t)ZDIM * K2 + 255) / 256, 256>>>(W2, U2);
    embw1_kernel<<<dim3(ZDIM / 64, (VOCAB + 63) / 64), 256>>>(emb, W1, b1);

    dim3 grid(16, 16);   // unit tiles x batch tiles = 256 CTAs, 2 per SM
    int q = 0, p = 0;
    for (int t = 0; t < SEQ; ++t) {
        lstm_tc<<<grid, 256>>>(tokens, b2, t, q, p, 0);
        lstm_tc<<<grid, 256>>>(tokens, b2, t, q, p, 1);
        q ^= 1; p ^= 1;
    }
    out_kernel<<<BATCH / 8, 256>>>(Wout, bout, out);
}

// round 13
// speedup vs baseline: 1.1522x; 1.1499x over previous
#include <cuda_runtime.h>
#include <cuda_bf16.h>
#include <cstdint>

#define VOCAB 10000
#define VPAD  10112           // 79*128, padded vocab rows
#define EMB   100
#define SEQ   80
#define BATCH 1024
#define UNITS 512
#define ZDIM  2048            // 4*UNITS
#define K1    512             // layer1 K (pure bf16)
#define K2    1024            // layer2 K ([h1|h2])

// ---------------- device scratch (static, no allocations) ----------------
__device__ float         g_EmbW1[(size_t)VOCAB * ZDIM];       // emb@W1+b1 fp32 (82MB)
__device__ __nv_bfloat16 g_embB[(size_t)VPAD * 128];          // emb bf16, K padded 100->128
__device__ __nv_bfloat16 g_W1T [(size_t)ZDIM * 128];          // W1^T bf16 [n][k], padded
__device__ __nv_bfloat16 g_B1[(size_t)ZDIM * K1];             // [n][k]  U1^T  bf16
__device__ __nv_bfloat16 g_B2[(size_t)ZDIM * K2];             // [n][k]  [W2;U2]^T bf16
__device__ __nv_bfloat16 g_A1[2][(size_t)BATCH * K1];         // h1 bf16, ping-pong
__device__ __nv_bfloat16 g_A2[2][(size_t)BATCH * K2];         // [h1 | h2] bf16, ping-pong
__device__ float         g_H2f[(size_t)BATCH * UNITS];        // fp32 h2 for output head
__device__ float         g_C1[(size_t)BATCH * UNITS];
__device__ float         g_C2[(size_t)BATCH * UNITS];

// ---------------- helpers ----------------
__device__ __forceinline__ uint32_t smem_u32(const void* p) {
    uint32_t a;
    asm("{ .reg .u64 t; cvta.to.shared.u64 t, %1; cvt.u32.u64 %0, t; }" : "=r"(a) : "l"(p));
    return a;
}
__device__ __forceinline__ void cp16(uint32_t sa, const void* g) {
    asm volatile("cp.async.cg.shared.global [%0], [%1], 16;" :: "r"(sa), "l"(g));
}
#define CP_COMMIT() asm volatile("cp.async.commit_group;")

__device__ __forceinline__ void ldmA(uint32_t a, uint32_t* r) {
    asm volatile("ldmatrix.sync.aligned.m8n8.x4.shared.b16 {%0,%1,%2,%3}, [%4];"
                 : "=r"(r[0]), "=r"(r[1]), "=r"(r[2]), "=r"(r[3]) : "r"(a));
}
// B stored [n][k]: NO trans (verified R5/R6).
__device__ __forceinline__ void ldmB(uint32_t a, uint32_t* r) {
    asm volatile("ldmatrix.sync.aligned.m8n8.x2.shared.b16 {%0,%1}, [%2];"
                 : "=r"(r[0]), "=r"(r[1]) : "r"(a));
}
__device__ __forceinline__ void mma16816(float* c, const uint32_t* a, const uint32_t* b) {
    asm volatile("mma.sync.aligned.m16n8k16.row.col.f32.bf16.bf16.f32 "
                 "{%0,%1,%2,%3},{%4,%5,%6,%7},{%8,%9},{%0,%1,%2,%3};"
                 : "+f"(c[0]), "+f"(c[1]), "+f"(c[2]), "+f"(c[3])
                 : "r"(a[0]), "r"(a[1]), "r"(a[2]), "r"(a[3]), "r"(b[0]), "r"(b[1]));
}
__device__ __forceinline__ float sigm(float x) { return __fdividef(1.0f, 1.0f + __expf(-x)); }

// ---------------- init / prep ----------------
__global__ void zero_state() {
    size_t i = (size_t)blockIdx.x * blockDim.x + threadIdx.x;
    size_t stride = (size_t)gridDim.x * blockDim.x;
    for (size_t k = i; k < (size_t)BATCH * K1; k += stride) { g_A1[0][k] = __nv_bfloat16(0.f); g_A1[1][k] = __nv_bfloat16(0.f); }
    for (size_t k = i; k < (size_t)BATCH * K2; k += stride) { g_A2[0][k] = __nv_bfloat16(0.f); g_A2[1][k] = __nv_bfloat16(0.f); }
    for (size_t k = i; k < (size_t)BATCH * UNITS; k += stride) { g_C1[k] = 0.f; g_C2[k] = 0.f; }
}

// bf16 conversions for embw1 HMMA: embB [VPAD][128], W1T [2048][128] (zero-padded K)
__global__ void cvt_inputs(const float* __restrict__ emb, const float* __restrict__ W1) {
    size_t i = (size_t)blockIdx.x * blockDim.x + threadIdx.x;
    size_t ne = (size_t)VPAD * 128;
    if (i < ne) {
        int v = (int)(i >> 7), k = (int)(i & 127);
        g_embB[i] = (v < VOCAB && k < EMB) ? __float2bfloat16(emb[v * EMB + k]) : __nv_bfloat16(0.f);
    }
    size_t j = i;  // reuse same range for W1T (smaller)
    if (j < (size_t)ZDIM * 128) {
        int n = (int)(j >> 7), k = (int)(j & 127);
        g_W1T[j] = (k < EMB) ? __float2bfloat16(W1[k * ZDIM + n]) : __nv_bfloat16(0.f);
    }
}

__global__ void make_B1(const float* __restrict__ U1) {
    size_t i = (size_t)blockIdx.x * blockDim.x + threadIdx.x;
    if (i >= (size_t)ZDIM * K1) return;
    int n = (int)(i / K1), k = (int)(i % K1);
    g_B1[i] = __float2bfloat16(U1[k * ZDIM + n]);
}

__global__ void make_B2(const float* __restrict__ W2, const float* __restrict__ U2) {
    size_t i = (size_t)blockIdx.x * blockDim.x + threadIdx.x;
    if (i >= (size_t)ZDIM * K2) return;
    int n = (int)(i / K2), k = (int)(i % K2);
    float w = (k < 512) ? W2[k * ZDIM + n] : U2[(k - 512) * ZDIM + n];
    g_B2[i] = __float2bfloat16(w);
}

#define ROWB 80

// EmbW1 = embB @ W1T^T + b1 via HMMA. grid (16, 79), BM=128, BN=128, K=128 (4 k-tiles).
__global__ __launch_bounds__(256) void embw1_mma(const float* __restrict__ b1) {
    __shared__ __align__(128) char smA[2][128 * ROWB];
    __shared__ __align__(128) char smB[2][128 * ROWB];

    const int tid = threadIdx.x;
    const int wid = tid >> 5, lane = tid & 31;
    const int warp_m = wid >> 2, warp_n = wid & 3;
    const int rowTile = blockIdx.y * 128, colTile = blockIdx.x * 128;

    const uint32_t sA0 = smem_u32(smA[0]), sA1 = smem_u32(smA[1]);
    const uint32_t sB0 = smem_u32(smB[0]), sB1 = smem_u32(smB[1]);

    const char* Agc = (const char*)g_embB;
    const char* Bgc = (const char*)g_W1T;
    const size_t strideBy = 256;   // 128 bf16

    int l_r[4], l_c[4];
    uint32_t l_so[4];
    size_t l_aoff[4], l_boff[4];
#pragma unroll
    for (int i = 0; i < 4; ++i) {
        int id = i * 256 + tid;
        int idx = id & 511;
        l_r[i] = idx >> 2; l_c[i] = idx & 3;
        l_so[i] = (uint32_t)(l_r[i] * ROWB + l_c[i] * 16);
        l_aoff[i] = (size_t)(rowTile + l_r[i]) * strideBy + l_c[i] * 16;
        l_boff[i] = (size_t)(colTile + l_r[i]) * strideBy + l_c[i] * 16;   // natural col mapping
    }

    float acc[4][4][4];
#pragma unroll
    for (int mi = 0; mi < 4; ++mi)
#pragma unroll
        for (int g = 0; g < 4; ++g)
#pragma unroll
            for (int j = 0; j < 4; ++j) acc[mi][g][j] = 0.0f;

    const int a_row = warp_m * 64 + (lane & 7) + ((lane >> 3) & 1) * 8;
    const int a_c16 = (lane >> 4) & 1;
    const int l15 = lane & 15;
    const int b_row = warp_n * 8 + (l15 & 7);
    const int b_c16 = l15 >> 3;

    // preload tile 0
#pragma unroll
    for (int i = 0; i < 4; ++i) {
        int id = i * 256 + tid;
        if (id < 512) cp16(sA0 + l_so[i], Agc + l_aoff[i]);
        else          cp16(sB0 + l_so[i], Bgc + l_boff[i]);
    }
    CP_COMMIT();

    const int NT = 4;
    for (int kt = 0; kt < NT; ++kt) {
        int b = kt & 1;
        uint32_t sA = b ? sA1 : sA0;
        uint32_t sB = b ? sB1 : sB0;
        if (kt + 1 < NT) {
            uint32_t dA = b ? sA0 : sA1;
            uint32_t dB = b ? sB0 : sB1;
            size_t go = (size_t)(kt + 1) * 64;
#pragma unroll
            for (int i = 0; i < 4; ++i) {
                int id = i * 256 + tid;
                if (id < 512) cp16(dA + l_so[i], Agc + l_aoff[i] + go);
                else          cp16(dB + l_so[i], Bgc + l_boff[i] + go);
            }
            CP_COMMIT();
            asm volatile("cp.async.wait_group 1;");
        } else {
            asm volatile("cp.async.wait_group 0;");
        }
        __syncthreads();
#pragma unroll
        for (int ks = 0; ks < 2; ++ks) {
            uint32_t af[4][4], bf[4][2];
#pragma unroll
            for (int mi = 0; mi < 4; ++mi)
                ldmA(sA + (uint32_t)((a_row + mi * 16) * ROWB + ks * 32 + a_c16 * 16), af[mi]);
#pragma unroll
            for (int g = 0; g < 4; ++g)
                ldmB(sB + (uint32_t)((b_row + g * 32) * ROWB + ks * 32 + b_c16 * 16), bf[g]);
#pragma unroll
            for (int mi = 0; mi < 4; ++mi)
#pragma unroll
                for (int g = 0; g < 4; ++g)
                    mma16816(acc[mi][g], af[mi], bf[g]);
        }
        __syncthreads();
    }

    // epilogue: EmbW1[row][c] = acc + b1[c]
#pragma unroll
    for (int mi = 0; mi < 4; ++mi) {
#pragma unroll
        for (int h = 0; h < 2; ++h) {
            int row = rowTile + warp_m * 64 + mi * 16 + (lane >> 2) + h * 8;
            if (row >= VOCAB) continue;
#pragma unroll
            for (int g = 0; g < 4; ++g) {
                int c = colTile + g * 32 + warp_n * 8 + (lane & 3) * 2;
                float2 bb = *(const float2*)(b1 + c);
                float2 o = make_float2(acc[mi][g][h * 2 + 0] + bb.x,
                                       acc[mi][g][h * 2 + 1] + bb.y);
                *(float2*)(g_EmbW1 + (size_t)row * ZDIM + c) = o;
            }
        }
    }
}

// ---------------- fused per-timestep kernel ----------------
// step body: BM=128, BN=128 z-cols, BK=32 double-buffered (verified R6/R7 structure)
template<int KP, int LAYER>
__device__ __forceinline__ void step_body(
    const int* __restrict__ tokens, const float* __restrict__ b2, int t,
    const __nv_bfloat16* __restrict__ Ag, const __nv_bfloat16* __restrict__ Bg,
    float* __restrict__ Cst, __nv_bfloat16* __restrict__ d1, __nv_bfloat16* __restrict__ d2,
    int rowTile, int uTile, uint32_t sA0, uint32_t sA1, uint32_t sB0, uint32_t sB1,
    int tid, int warp_m, int warp_n, int lane)
{
    const size_t strideBy = (size_t)KP * 2;
    const char* Agc = (const char*)Ag;
    const char* Bgc = (const char*)Bg;

    int l_r[4], l_c[4];
    uint32_t l_so[4];
    size_t l_aoff[4], l_boff[4];
#pragma unroll
    for (int i = 0; i < 4; ++i) {
        int id = i * 256 + tid;
        int idx = id & 511;
        l_r[i] = idx >> 2; l_c[i] = idx & 3;
        l_so[i] = (uint32_t)(l_r[i] * ROWB + l_c[i] * 16);
        l_aoff[i] = (size_t)(rowTile + l_r[i]) * strideBy + l_c[i] * 16;
        int n = ((l_r[i] >> 5) * 512) + uTile + (l_r[i] & 31);
        l_boff[i] = (size_t)n * strideBy + l_c[i] * 16;
    }

    float acc[4][4][4];
#pragma unroll
    for (int mi = 0; mi < 4; ++mi)
#pragma unroll
        for (int g = 0; g < 4; ++g)
#pragma unroll
            for (int j = 0; j < 4; ++j) acc[mi][g][j] = 0.0f;

    const int a_row = warp_m * 64 + (lane & 7) + ((lane >> 3) & 1) * 8;
    const int a_c16 = (lane >> 4) & 1;
    const int l15 = lane & 15;
    const int b_row = warp_n * 8 + (l15 & 7);
    const int b_c16 = l15 >> 3;
    const int u0 = uTile + warp_n * 8 + (lane & 3) * 2;

    const int NT = KP >> 5;

    // preload tile 0
#pragma unroll
    for (int i = 0; i < 4; ++i) {
        int id = i * 256 + tid;
        if (id < 512) cp16(sA0 + l_so[i], Agc + l_aoff[i]);
        else          cp16(sB0 + l_so[i], Bgc + l_boff[i]);
    }
    CP_COMMIT();

    for (int kt = 0; kt < NT; ++kt) {
        int b = kt & 1;
        uint32_t sA = b ? sA1 : sA0;
        uint32_t sB = b ? sB1 : sB0;
        if (kt + 1 < NT) {
            uint32_t dA = b ? sA0 : sA1;
            uint32_t dB = b ? sB0 : sB1;
            size_t go = (size_t)(kt + 1) * 64;
#pragma unroll
            for (int i = 0; i < 4; ++i) {
                int id = i * 256 + tid;
                if (id < 512) cp16(dA + l_so[i], Agc + l_aoff[i] + go);
                else          cp16(dB + l_so[i], Bgc + l_boff[i] + go);
            }
            CP_COMMIT();
            asm volatile("cp.async.wait_group 1;");
        } else {
            asm volatile("cp.async.wait_group 0;");
        }
        __syncthreads();

#pragma unroll
        for (int ks = 0; ks < 2; ++ks) {
            uint32_t af[4][4], bf[4][2];
#pragma unroll
            for (int mi = 0; mi < 4; ++mi)
                ldmA(sA + (uint32_t)((a_row + mi * 16) * ROWB + ks * 32 + a_c16 * 16), af[mi]);
#pragma unroll
            for (int g = 0; g < 4; ++g)
                ldmB(sB + (uint32_t)((b_row + g * 32) * ROWB + ks * 32 + b_c16 * 16), bf[g]);
#pragma unroll
            for (int mi = 0; mi < 4; ++mi)
#pragma unroll
                for (int g = 0; g < 4; ++g)
                    mma16816(acc[mi][g], af[mi], bf[g]);
        }
        __syncthreads();
    }

    // epilogue (thread-local gates; verified layout)
#pragma unroll
    for (int mi = 0; mi < 4; ++mi) {
#pragma unroll
        for (int h = 0; h < 2; ++h) {
            int row = rowTile + warp_m * 64 + mi * 16 + (lane >> 2) + h * 8;
            const float* Xrow;
            if (LAYER == 0) Xrow = g_EmbW1 + (size_t)tokens[row * SEQ + t] * ZDIM;
            else            Xrow = b2;
            float2 xz[4];
#pragma unroll
            for (int g = 0; g < 4; ++g) xz[g] = *(const float2*)(Xrow + g * 512 + u0);

            float zi0 = acc[mi][0][h * 2 + 0] + xz[0].x, zi1 = acc[mi][0][h * 2 + 1] + xz[0].y;
            float zf0 = acc[mi][1][h * 2 + 0] + xz[1].x, zf1 = acc[mi][1][h * 2 + 1] + xz[1].y;
            float zg0 = acc[mi][2][h * 2 + 0] + xz[2].x, zg1 = acc[mi][2][h * 2 + 1] + xz[2].y;
            float zo0 = acc[mi][3][h * 2 + 0] + xz[3].x, zo1 = acc[mi][3][h * 2 + 1] + xz[3].y;

            float* cp = Cst + (size_t)row * UNITS + u0;
            float2 c = *(float2*)cp;
            c.x = sigm(zf0) * c.x + sigm(zi0) * tanhf(zg0);
            c.y = sigm(zf1) * c.y + sigm(zi1) * tanhf(zg1);
            *(float2*)cp = c;
            float hv0 = sigm(zo0) * tanhf(c.x);
            float hv1 = sigm(zo1) * tanhf(c.y);

            __nv_bfloat16 bh0 = __float2bfloat16(hv0);
            __nv_bfloat16 bh1 = __float2bfloat16(hv1);
            uint32_t hiP = ((uint32_t)*(unsigned short*)&bh1 << 16) | *(unsigned short*)&bh0;

            if (LAYER == 0) {
                *(uint32_t*)(d1 + (size_t)row * K1 + u0) = hiP;          // h1 -> A1[a^1]
                *(uint32_t*)(d2 + (size_t)row * K2 + u0) = hiP;          // h1 -> A2[a].h1
            } else {
                *(uint32_t*)(d1 + (size_t)row * K2 + 512 + u0) = hiP;    // h2 -> A2[a^1].h2
                *(float2*)(g_H2f + (size_t)row * UNITS + u0) = make_float2(hv0, hv1);
            }
        }
    }
}

// launch tau runs layer1(t=tau) [y<8] and layer2(t=tau-1) [y>=8] concurrently.
// Independence: both depend only on state produced by launch tau-1.
__global__ __launch_bounds__(256) void lstm_fused(const int* __restrict__ tokens,
                                                  const float* __restrict__ b2, int tau) {
    __shared__ __align__(128) char smA[2][128 * ROWB];
    __shared__ __align__(128) char smB[2][128 * ROWB];

    const int tid = threadIdx.x;
    const int wid = tid >> 5, lane = tid & 31;
    const int warp_m = wid >> 2, warp_n = wid & 3;
    const bool isL1 = blockIdx.y < 8;
    const int rowTile = (blockIdx.y & 7) * 128;
    const int uTile = blockIdx.x * 32;
    const uint32_t sA0 = smem_u32(smA[0]), sA1 = smem_u32(smA[1]);
    const uint32_t sB0 = smem_u32(smB[0]), sB1 = smem_u32(smB[1]);

    if (isL1) {
        if (tau >= SEQ) return;
        const int t = tau, a = t & 1;
        step_body<K1, 0>(tokens, b2, t, g_A1[a], g_B1, g_C1,
                         g_A1[a ^ 1], g_A2[a], rowTile, uTile,
                         sA0, sA1, sB0, sB1, tid, warp_m, warp_n, lane);
    } else {
        if (tau == 0) return;
        const int t = tau - 1, a = t & 1;
        step_body<K2, 1>(tokens, b2, t, g_A2[a], g_B2, g_C2,
                         g_A2[a ^ 1], nullptr, rowTile, uTile,
                         sA0, sA1, sB0, sB1, tid, warp_m, warp_n, lane);
    }
}

// ---------------- output head ----------------
__global__ void out_kernel(const float* __restrict__ Wout, const float* __restrict__ bout,
                           float* __restrict__ out) {
    int row = (blockIdx.x * blockDim.x + threadIdx.x) >> 5;
    int lane = threadIdx.x & 31;
    float s = 0.0f;
    for (int k = lane; k < UNITS; k += 32)
        s += g_H2f[(size_t)row * UNITS + k] * Wout[k];
#pragma unroll
    for (int off = 16; off; off >>= 1) s += __shfl_down_sync(0xffffffffu, s, off);
    if (lane == 0) out[row] = sigm(s + bout[0]);
}

// ---------------- launch ----------------
extern "C" void kernel_launch(void* const* d_in, const int* in_sizes, int n_in,
                              void* d_out, int out_size) {
    const int*   tokens = (const int*)d_in[0];
    const float* emb    = (const float*)d_in[1];
    const float* W1     = (const float*)d_in[2];
    const float* U1     = (const float*)d_in[3];
    const float* b1     = (const float*)d_in[4];
    const float* W2     = (const float*)d_in[5];
    const float* U2     = (const float*)d_in[6];
    const float* b2     = (const float*)d_in[7];
    const float* Wout   = (const float*)d_in[8];
    const float* bout   = (const float*)d_in[9];
    float* out = (float*)d_out;

    zero_state<<<1024, 256>>>();
    cvt_inputs<<<((size_t)VPAD * 128 + 255) / 256, 256>>>(emb, W1);
    make_B1<<<((size_t)ZDIM * K1 + 255) / 256, 256>>>(U1);
    make_B2<<<((size_t)ZDIM * K2 + 255) / 256, 256>>>(W2, U2);
    embw1_mma<<<dim3(16, VPAD / 128), 256>>>(b1);

    dim3 grid(16, 16);   // y<8: layer1 tiles, y>=8: layer2 tiles
    for (int tau = 0; tau <= SEQ; ++tau)
        lstm_fused<<<grid, 256>>>(tokens, b2, tau);

    out_kernel<<<BATCH / 8, 256>>>(Wout, bout, out);
}

// round 14
// speedup vs baseline: 1.1523x; 1.0000x over previous
#include <cuda_runtime.h>
#include <cuda_bf16.h>
#include <cstdint>

#define VOCAB 10000
#define VPAD  10112           // 79*128, padded vocab rows
#define EMB   100
#define SEQ   80
#define BATCH 1024
#define UNITS 512
#define ZDIM  2048            // 4*UNITS
#define K1    512             // layer1 K (pure bf16)
#define K2    1024            // layer2 K ([h1|h2])

// ---------------- device scratch (static, no allocations) ----------------
__device__ float         g_EmbW1[(size_t)VOCAB * ZDIM];       // emb@W1+b1 fp32 (82MB)
__device__ __nv_bfloat16 g_embB[(size_t)VPAD * 128];          // emb bf16, K padded 100->128
__device__ __nv_bfloat16 g_W1T [(size_t)ZDIM * 128];          // W1^T bf16 [n][k], padded
__device__ __nv_bfloat16 g_B1[(size_t)ZDIM * K1];             // [n][k]  U1^T  bf16
__device__ __nv_bfloat16 g_B2[(size_t)ZDIM * K2];             // [n][k]  [W2;U2]^T bf16
__device__ __nv_bfloat16 g_A1[2][(size_t)BATCH * K1];         // h1 bf16, ping-pong
__device__ __nv_bfloat16 g_A2[2][(size_t)BATCH * K2];         // [h1 | h2] bf16, ping-pong
__device__ float         g_H2f[(size_t)BATCH * UNITS];        // fp32 h2 for output head
__device__ float         g_C1[(size_t)BATCH * UNITS];
__device__ float         g_C2[(size_t)BATCH * UNITS];

// ---------------- helpers ----------------
__device__ __forceinline__ uint32_t smem_u32(const void* p) {
    uint32_t a;
    asm("{ .reg .u64 t; cvta.to.shared.u64 t, %1; cvt.u32.u64 %0, t; }" : "=r"(a) : "l"(p));
    return a;
}
__device__ __forceinline__ void cp16(uint32_t sa, const void* g) {
    asm volatile("cp.async.cg.shared.global [%0], [%1], 16;" :: "r"(sa), "l"(g));
}
#define CP_COMMIT() asm volatile("cp.async.commit_group;")

__device__ __forceinline__ void ldmA(uint32_t a, uint32_t* r) {
    asm volatile("ldmatrix.sync.aligned.m8n8.x4.shared.b16 {%0,%1,%2,%3}, [%4];"
                 : "=r"(r[0]), "=r"(r[1]), "=r"(r[2]), "=r"(r[3]) : "r"(a));
}
// B stored [n][k]: NO trans (verified R5/R6).
__device__ __forceinline__ void ldmB(uint32_t a, uint32_t* r) {
    asm volatile("ldmatrix.sync.aligned.m8n8.x2.shared.b16 {%0,%1}, [%2];"
                 : "=r"(r[0]), "=r"(r[1]) : "r"(a));
}
__device__ __forceinline__ void mma16816(float* c, const uint32_t* a, const uint32_t* b) {
    asm volatile("mma.sync.aligned.m16n8k16.row.col.f32.bf16.bf16.f32 "
                 "{%0,%1,%2,%3},{%4,%5,%6,%7},{%8,%9},{%0,%1,%2,%3};"
                 : "+f"(c[0]), "+f"(c[1]), "+f"(c[2]), "+f"(c[3])
                 : "r"(a[0]), "r"(a[1]), "r"(a[2]), "r"(a[3]), "r"(b[0]), "r"(b[1]));
}
// MUFU fast path: single-instruction tanh; sigmoid via identity 0.5*tanh(x/2)+0.5
__device__ __forceinline__ float ftanh(float x) {
    float y; asm("tanh.approx.f32 %0, %1;" : "=f"(y) : "f"(x)); return y;
}
__device__ __forceinline__ float fsigm(float x) { return fmaf(0.5f, ftanh(0.5f * x), 0.5f); }
__device__ __forceinline__ float sigm(float x) {   // accurate path (output head)
    return __fdividef(1.0f, 1.0f + __expf(-x));
}

// ---------------- merged prep kernel ----------------
__global__ void prep_all(const float* __restrict__ emb, const float* __restrict__ W1,
                         const float* __restrict__ U1, const float* __restrict__ W2,
                         const float* __restrict__ U2) {
    size_t i0 = (size_t)blockIdx.x * blockDim.x + threadIdx.x;
    size_t gs = (size_t)gridDim.x * blockDim.x;
    const __nv_bfloat16 z = __float2bfloat16(0.f);
    for (size_t i = i0; i < (size_t)BATCH * K1; i += gs) { g_A1[0][i] = z; g_A1[1][i] = z; }
    for (size_t i = i0; i < (size_t)BATCH * K2; i += gs) { g_A2[0][i] = z; g_A2[1][i] = z; }
    for (size_t i = i0; i < (size_t)BATCH * UNITS; i += gs) { g_C1[i] = 0.f; g_C2[i] = 0.f; }
    for (size_t i = i0; i < (size_t)VPAD * 128; i += gs) {
        int v = (int)(i >> 7), k = (int)(i & 127);
        g_embB[i] = (v < VOCAB && k < EMB) ? __float2bfloat16(emb[v * EMB + k]) : z;
    }
    for (size_t i = i0; i < (size_t)ZDIM * 128; i += gs) {
        int n = (int)(i >> 7), k = (int)(i & 127);
        g_W1T[i] = (k < EMB) ? __float2bfloat16(W1[k * ZDIM + n]) : z;
    }
    for (size_t i = i0; i < (size_t)ZDIM * K1; i += gs) {
        int n = (int)(i / K1), k = (int)(i % K1);
        g_B1[i] = __float2bfloat16(U1[k * ZDIM + n]);
    }
    for (size_t i = i0; i < (size_t)ZDIM * K2; i += gs) {
        int n = (int)(i / K2), k = (int)(i % K2);
        float w = (k < 512) ? W2[k * ZDIM + n] : U2[(k - 512) * ZDIM + n];
        g_B2[i] = __float2bfloat16(w);
    }
}

#define ROWB 80
#define TILEB (128 * ROWB)

// EmbW1 = embB @ W1T^T + b1 via HMMA. grid (16, 79), BM=128, BN=128, K=128 (verified R12).
__global__ __launch_bounds__(256) void embw1_mma(const float* __restrict__ b1) {
    __shared__ __align__(128) char smA[2][128 * ROWB];
    __shared__ __align__(128) char smB[2][128 * ROWB];

    const int tid = threadIdx.x;
    const int wid = tid >> 5, lane = tid & 31;
    const int warp_m = wid >> 2, warp_n = wid & 3;
    const int rowTile = blockIdx.y * 128, colTile = blockIdx.x * 128;

    const uint32_t sA0 = smem_u32(smA[0]), sA1 = smem_u32(smA[1]);
    const uint32_t sB0 = smem_u32(smB[0]), sB1 = smem_u32(smB[1]);

    const char* Agc = (const char*)g_embB;
    const char* Bgc = (const char*)g_W1T;
    const size_t strideBy = 256;

    int l_r[4], l_c[4];
    uint32_t l_so[4];
    size_t l_aoff[4], l_boff[4];
#pragma unroll
    for (int i = 0; i < 4; ++i) {
        int id = i * 256 + tid;
        int idx = id & 511;
        l_r[i] = idx >> 2; l_c[i] = idx & 3;
        l_so[i] = (uint32_t)(l_r[i] * ROWB + l_c[i] * 16);
        l_aoff[i] = (size_t)(rowTile + l_r[i]) * strideBy + l_c[i] * 16;
        l_boff[i] = (size_t)(colTile + l_r[i]) * strideBy + l_c[i] * 16;
    }

    float acc[4][4][4];
#pragma unroll
    for (int mi = 0; mi < 4; ++mi)
#pragma unroll
        for (int g = 0; g < 4; ++g)
#pragma unroll
            for (int j = 0; j < 4; ++j) acc[mi][g][j] = 0.0f;

    const int a_row = warp_m * 64 + (lane & 7) + ((lane >> 3) & 1) * 8;
    const int a_c16 = (lane >> 4) & 1;
    const int l15 = lane & 15;
    const int b_row = warp_n * 8 + (l15 & 7);
    const int b_c16 = l15 >> 3;

#pragma unroll
    for (int i = 0; i < 4; ++i) {
        int id = i * 256 + tid;
        if (id < 512) cp16(sA0 + l_so[i], Agc + l_aoff[i]);
        else          cp16(sB0 + l_so[i], Bgc + l_boff[i]);
    }
    CP_COMMIT();

    const int NT = 4;
    for (int kt = 0; kt < NT; ++kt) {
        int b = kt & 1;
        uint32_t sA = b ? sA1 : sA0;
        uint32_t sB = b ? sB1 : sB0;
        if (kt + 1 < NT) {
            uint32_t dA = b ? sA0 : sA1;
            uint32_t dB = b ? sB0 : sB1;
            size_t go = (size_t)(kt + 1) * 64;
#pragma unroll
            for (int i = 0; i < 4; ++i) {
                int id = i * 256 + tid;
                if (id < 512) cp16(dA + l_so[i], Agc + l_aoff[i] + go);
                else          cp16(dB + l_so[i], Bgc + l_boff[i] + go);
            }
            CP_COMMIT();
            asm volatile("cp.async.wait_group 1;");
        } else {
            asm volatile("cp.async.wait_group 0;");
        }
        __syncthreads();
#pragma unroll
        for (int ks = 0; ks < 2; ++ks) {
            uint32_t af[4][4], bf[4][2];
#pragma unroll
            for (int mi = 0; mi < 4; ++mi)
                ldmA(sA + (uint32_t)((a_row + mi * 16) * ROWB + ks * 32 + a_c16 * 16), af[mi]);
#pragma unroll
            for (int g = 0; g < 4; ++g)
                ldmB(sB + (uint32_t)((b_row + g * 32) * ROWB + ks * 32 + b_c16 * 16), bf[g]);
#pragma unroll
            for (int mi = 0; mi < 4; ++mi)
#pragma unroll
                for (int g = 0; g < 4; ++g)
                    mma16816(acc[mi][g], af[mi], bf[g]);
        }
        __syncthreads();
    }

#pragma unroll
    for (int mi = 0; mi < 4; ++mi) {
#pragma unroll
        for (int h = 0; h < 2; ++h) {
            int row = rowTile + warp_m * 64 + mi * 16 + (lane >> 2) + h * 8;
            if (row >= VOCAB) continue;
#pragma unroll
            for (int g = 0; g < 4; ++g) {
                int c = colTile + g * 32 + warp_n * 8 + (lane & 3) * 2;
                float2 bb = *(const float2*)(b1 + c);
                float2 o = make_float2(acc[mi][g][h * 2 + 0] + bb.x,
                                       acc[mi][g][h * 2 + 1] + bb.y);
                *(float2*)(g_EmbW1 + (size_t)row * ZDIM + c) = o;
            }
        }
    }
}

// ---------------- fused per-timestep kernel (3-stage pipeline, 1 sync/tile) ----------------
template<int KP, int LAYER>
__device__ __forceinline__ void step_body(
    const int* __restrict__ tokens, const float* __restrict__ b2, int t,
    const __nv_bfloat16* __restrict__ Ag, const __nv_bfloat16* __restrict__ Bg,
    float* __restrict__ Cst, __nv_bfloat16* __restrict__ d1, __nv_bfloat16* __restrict__ d2,
    int rowTile, int uTile, uint32_t sbA, uint32_t sbB,
    int tid, int warp_m, int warp_n, int lane)
{
    const size_t strideBy = (size_t)KP * 2;
    const char* Agc = (const char*)Ag;
    const char* Bgc = (const char*)Bg;

    int l_r[4], l_c[4];
    uint32_t l_so[4];
    size_t l_aoff[4], l_boff[4];
#pragma unroll
    for (int i = 0; i < 4; ++i) {
        int id = i * 256 + tid;
        int idx = id & 511;
        l_r[i] = idx >> 2; l_c[i] = idx & 3;
        l_so[i] = (uint32_t)(l_r[i] * ROWB + l_c[i] * 16);
        l_aoff[i] = (size_t)(rowTile + l_r[i]) * strideBy + l_c[i] * 16;
        int n = ((l_r[i] >> 5) * 512) + uTile + (l_r[i] & 31);
        l_boff[i] = (size_t)n * strideBy + l_c[i] * 16;
    }

#define ISSUE(ktv) do {                                                          \
        size_t go = (size_t)(ktv) * 64;                                          \
        uint32_t off = (uint32_t)((ktv) % 3) * TILEB;                            \
        _Pragma("unroll")                                                        \
        for (int i = 0; i < 4; ++i) {                                            \
            int id = i * 256 + tid;                                              \
            if (id < 512) cp16(sbA + off + l_so[i], Agc + l_aoff[i] + go);       \
            else          cp16(sbB + off + l_so[i], Bgc + l_boff[i] + go);       \
        }                                                                        \
        CP_COMMIT();                                                             \
    } while (0)

    float acc[4][4][4];
#pragma unroll
    for (int mi = 0; mi < 4; ++mi)
#pragma unroll
        for (int g = 0; g < 4; ++g)
#pragma unroll
            for (int j = 0; j < 4; ++j) acc[mi][g][j] = 0.0f;

    const int a_row = warp_m * 64 + (lane & 7) + ((lane >> 3) & 1) * 8;
    const int a_c16 = (lane >> 4) & 1;
    const int l15 = lane & 15;
    const int b_row = warp_n * 8 + (l15 & 7);
    const int b_c16 = l15 >> 3;
    const int u0 = uTile + warp_n * 8 + (lane & 3) * 2;

    const int NT = KP >> 5;

    ISSUE(0);
    ISSUE(1);

    for (int kt = 0; kt < NT; ++kt) {
        if (kt == NT - 1) asm volatile("cp.async.wait_group 0;");
        else              asm volatile("cp.async.wait_group 1;");   // tile kt retired
        __syncthreads();   // all warps done computing tile kt-1; buffer (kt+2)%3 free
        if (kt + 2 < NT) ISSUE(kt + 2);

        uint32_t sA = sbA + (uint32_t)(kt % 3) * TILEB;
        uint32_t sB = sbB + (uint32_t)(kt % 3) * TILEB;
#pragma unroll
        for (int ks = 0; ks < 2; ++ks) {
            uint32_t af[4][4], bf[4][2];
#pragma unroll
            for (int mi = 0; mi < 4; ++mi)
                ldmA(sA + (uint32_t)((a_row + mi * 16) * ROWB + ks * 32 + a_c16 * 16), af[mi]);
#pragma unroll
            for (int g = 0; g < 4; ++g)
                ldmB(sB + (uint32_t)((b_row + g * 32) * ROWB + ks * 32 + b_c16 * 16), bf[g]);
#pragma unroll
            for (int mi = 0; mi < 4; ++mi)
#pragma unroll
                for (int g = 0; g < 4; ++g)
                    mma16816(acc[mi][g], af[mi], bf[g]);
        }
    }
#undef ISSUE

    // epilogue (thread-local gates; layout verified R5/R6; MUFU fast transcendentals)
#pragma unroll
    for (int mi = 0; mi < 4; ++mi) {
#pragma unroll
        for (int h = 0; h < 2; ++h) {
            int row = rowTile + warp_m * 64 + mi * 16 + (lane >> 2) + h * 8;
            const float* Xrow;
            if (LAYER == 0) Xrow = g_EmbW1 + (size_t)tokens[row * SEQ + t] * ZDIM;
            else            Xrow = b2;
            float2 xz[4];
#pragma unroll
            for (int g = 0; g < 4; ++g) xz[g] = *(const float2*)(Xrow + g * 512 + u0);

            float zi0 = acc[mi][0][h * 2 + 0] + xz[0].x, zi1 = acc[mi][0][h * 2 + 1] + xz[0].y;
            float zf0 = acc[mi][1][h * 2 + 0] + xz[1].x, zf1 = acc[mi][1][h * 2 + 1] + xz[1].y;
            float zg0 = acc[mi][2][h * 2 + 0] + xz[2].x, zg1 = acc[mi][2][h * 2 + 1] + xz[2].y;
            float zo0 = acc[mi][3][h * 2 + 0] + xz[3].x, zo1 = acc[mi][3][h * 2 + 1] + xz[3].y;

            float* cp = Cst + (size_t)row * UNITS + u0;
            float2 c = *(float2*)cp;
            c.x = fsigm(zf0) * c.x + fsigm(zi0) * ftanh(zg0);
            c.y = fsigm(zf1) * c.y + fsigm(zi1) * ftanh(zg1);
            *(float2*)cp = c;
            float hv0 = fsigm(zo0) * ftanh(c.x);
            float hv1 = fsigm(zo1) * ftanh(c.y);

            __nv_bfloat16 bh0 = __float2bfloat16(hv0);
            __nv_bfloat16 bh1 = __float2bfloat16(hv1);
            uint32_t hiP = ((uint32_t)*(unsigned short*)&bh1 << 16) | *(unsigned short*)&bh0;

            if (LAYER == 0) {
                *(uint32_t*)(d1 + (size_t)row * K1 + u0) = hiP;          // h1 -> A1[a^1]
                *(uint32_t*)(d2 + (size_t)row * K2 + u0) = hiP;          // h1 -> A2[a].h1
            } else {
                *(uint32_t*)(d1 + (size_t)row * K2 + 512 + u0) = hiP;    // h2 -> A2[a^1].h2
                *(float2*)(g_H2f + (size_t)row * UNITS + u0) = make_float2(hv0, hv1);
            }
        }
    }
}

// launch tau runs layer1(t=tau) [y<8] and layer2(t=tau-1) [y>=8] concurrently (verified R12).
__global__ __launch_bounds__(256) void lstm_fused(const int* __restrict__ tokens,
                                                  const float* __restrict__ b2, int tau) {
    extern __shared__ __align__(128) char dynsm[];
    const uint32_t sbA = smem_u32(dynsm);
    const uint32_t sbB = sbA + 3 * TILEB;

    const int tid = threadIdx.x;
    const int wid = tid >> 5, lane = tid & 31;
    const int warp_m = wid >> 2, warp_n = wid & 3;
    const bool isL1 = blockIdx.y < 8;
    const int rowTile = (blockIdx.y & 7) * 128;
    const int uTile = blockIdx.x * 32;

    if (isL1) {
        if (tau >= SEQ) return;
        const int t = tau, a = t & 1;
        step_body<K1, 0>(tokens, b2, t, g_A1[a], g_B1, g_C1,
                         g_A1[a ^ 1], g_A2[a], rowTile, uTile, sbA, sbB,
                         tid, warp_m, warp_n, lane);
    } else {
        if (tau == 0) return;
        const int t = tau - 1, a = t & 1;
        step_body<K2, 1>(tokens, b2, t, g_A2[a], g_B2, g_C2,
                         g_A2[a ^ 1], nullptr, rowTile, uTile, sbA, sbB,
                         tid, warp_m, warp_n, lane);
    }
}

// ---------------- output head ----------------
__global__ void out_kernel(const float* __restrict__ Wout, const float* __restrict__ bout,
                           float* __restrict__ out) {
    int row = (blockIdx.x * blockDim.x + threadIdx.x) >> 5;
    int lane = threadIdx.x & 31;
    float s = 0.0f;
    for (int k = lane; k < UNITS; k += 32)
        s += g_H2f[(size_t)row * UNITS + k] * Wout[k];
#pragma unroll
    for (int off = 16; off; off >>= 1) s += __shfl_down_sync(0xffffffffu, s, off);
    if (lane == 0) out[row] = sigm(s + bout[0]);
}

// ---------------- launch ----------------
#define DYNSM (6 * TILEB)   // 61440 bytes: 3-stage A + B

extern "C" void kernel_launch(void* const* d_in, const int* in_sizes, int n_in,
                              void* d_out, int out_size) {
    const int*   tokens = (const int*)d_in[0];
    const float* emb    = (const float*)d_in[1];
    const float* W1     = (const float*)d_in[2];
    const float* U1     = (const float*)d_in[3];
    const float* b1     = (const float*)d_in[4];
    const float* W2     = (const float*)d_in[5];
    const float* U2     = (const float*)d_in[6];
    const float* b2     = (const float*)d_in[7];
    const float* Wout   = (const float*)d_in[8];
    const float* bout   = (const float*)d_in[9];
    float* out = (float*)d_out;

    static int smem_set = 0;
    if (!smem_set) {
        cudaFuncSetAttribute(lstm_fused, cudaFuncAttributeMaxDynamicSharedMemorySize, DYNSM);
        smem_set = 1;
    }

    prep_all<<<1024, 256>>>(emb, W1, U1, W2, U2);
    embw1_mma<<<dim3(16, VPAD / 128), 256>>>(b1);

    dim3 grid(16, 16);   // y<8: layer1 tiles, y>=8: layer2 tiles
    for (int tau = 0; tau <= SEQ; ++tau)
        lstm_fused<<<grid, 256, DYNSM>>>(tokens, b2, tau);

    out_kernel<<<BATCH / 8, 256>>>(Wout, bout, out);
}

// round 15
// speedup vs baseline: 1.1660x; 1.0119x over previous
#include <cuda_runtime.h>
#include <cuda_bf16.h>
#include <cstdint>

#define VOCAB 10000
#define VPAD  10112           // 79*128, padded vocab rows
#define EMB   100
#define SEQ   80
#define BATCH 1024
#define UNITS 512
#define ZDIM  2048            // 4*UNITS
#define K1    512             // layer1 K (pure bf16)
#define K2    1024            // layer2 K ([h1|h2])

// ---------------- device scratch (static, no allocations) ----------------
__device__ float         g_EmbW1[(size_t)VOCAB * ZDIM];       // emb@W1+b1 fp32 (82MB)
__device__ __nv_bfloat16 g_embB[(size_t)VPAD * 128];          // emb bf16, K padded 100->128
__device__ __nv_bfloat16 g_W1T [(size_t)ZDIM * 128];          // W1^T bf16 [n][k], padded
__device__ __nv_bfloat16 g_B1[(size_t)ZDIM * K1];             // [n][k]  U1^T  bf16
__device__ __nv_bfloat16 g_B2[(size_t)ZDIM * K2];             // [n][k]  [W2;U2]^T bf16
__device__ __nv_bfloat16 g_A1[2][(size_t)BATCH * K1];         // h1 bf16, ping-pong
__device__ __nv_bfloat16 g_A2[2][(size_t)BATCH * K2];         // [h1 | h2] bf16, ping-pong
__device__ float         g_H2f[(size_t)BATCH * UNITS];        // fp32 h2 for output head
__device__ float         g_C1[(size_t)BATCH * UNITS];
__device__ float         g_C2[(size_t)BATCH * UNITS];

// ---------------- helpers ----------------
__device__ __forceinline__ uint32_t smem_u32(const void* p) {
    uint32_t a;
    asm("{ .reg .u64 t; cvta.to.shared.u64 t, %1; cvt.u32.u64 %0, t; }" : "=r"(a) : "l"(p));
    return a;
}
__device__ __forceinline__ void cp16(uint32_t sa, const void* g) {
    asm volatile("cp.async.cg.shared.global [%0], [%1], 16;" :: "r"(sa), "l"(g));
}
#define CP_COMMIT() asm volatile("cp.async.commit_group;")

__device__ __forceinline__ void ldmA(uint32_t a, uint32_t* r) {
    asm volatile("ldmatrix.sync.aligned.m8n8.x4.shared.b16 {%0,%1,%2,%3}, [%4];"
                 : "=r"(r[0]), "=r"(r[1]), "=r"(r[2]), "=r"(r[3]) : "r"(a));
}
// B stored [n][k]: NO trans (verified R5/R6).
__device__ __forceinline__ void ldmB(uint32_t a, uint32_t* r) {
    asm volatile("ldmatrix.sync.aligned.m8n8.x2.shared.b16 {%0,%1}, [%2];"
                 : "=r"(r[0]), "=r"(r[1]) : "r"(a));
}
__device__ __forceinline__ void mma16816(float* c, const uint32_t* a, const uint32_t* b) {
    asm volatile("mma.sync.aligned.m16n8k16.row.col.f32.bf16.bf16.f32 "
                 "{%0,%1,%2,%3},{%4,%5,%6,%7},{%8,%9},{%0,%1,%2,%3};"
                 : "+f"(c[0]), "+f"(c[1]), "+f"(c[2]), "+f"(c[3])
                 : "r"(a[0]), "r"(a[1]), "r"(a[2]), "r"(a[3]), "r"(b[0]), "r"(b[1]));
}
// MUFU fast path: single-instruction tanh; sigmoid via identity 0.5*tanh(x/2)+0.5
__device__ __forceinline__ float ftanh(float x) {
    float y; asm("tanh.approx.f32 %0, %1;" : "=f"(y) : "f"(x)); return y;
}
__device__ __forceinline__ float fsigm(float x) { return fmaf(0.5f, ftanh(0.5f * x), 0.5f); }
__device__ __forceinline__ float sigm(float x) {   // accurate path (output head)
    return __fdividef(1.0f, 1.0f + __expf(-x));
}

// ---------------- merged prep kernel ----------------
__global__ void prep_all(const float* __restrict__ emb, const float* __restrict__ W1,
                         const float* __restrict__ U1, const float* __restrict__ W2,
                         const float* __restrict__ U2) {
    size_t i0 = (size_t)blockIdx.x * blockDim.x + threadIdx.x;
    size_t gs = (size_t)gridDim.x * blockDim.x;
    const __nv_bfloat16 z = __float2bfloat16(0.f);
    for (size_t i = i0; i < (size_t)BATCH * K1; i += gs) { g_A1[0][i] = z; g_A1[1][i] = z; }
    for (size_t i = i0; i < (size_t)BATCH * K2; i += gs) { g_A2[0][i] = z; g_A2[1][i] = z; }
    for (size_t i = i0; i < (size_t)BATCH * UNITS; i += gs) { g_C1[i] = 0.f; g_C2[i] = 0.f; }
    for (size_t i = i0; i < (size_t)VPAD * 128; i += gs) {
        int v = (int)(i >> 7), k = (int)(i & 127);
        g_embB[i] = (v < VOCAB && k < EMB) ? __float2bfloat16(emb[v * EMB + k]) : z;
    }
    for (size_t i = i0; i < (size_t)ZDIM * 128; i += gs) {
        int n = (int)(i >> 7), k = (int)(i & 127);
        g_W1T[i] = (k < EMB) ? __float2bfloat16(W1[k * ZDIM + n]) : z;
    }
    for (size_t i = i0; i < (size_t)ZDIM * K1; i += gs) {
        int n = (int)(i / K1), k = (int)(i % K1);
        g_B1[i] = __float2bfloat16(U1[k * ZDIM + n]);
    }
    for (size_t i = i0; i < (size_t)ZDIM * K2; i += gs) {
        int n = (int)(i / K2), k = (int)(i % K2);
        float w = (k < 512) ? W2[k * ZDIM + n] : U2[(k - 512) * ZDIM + n];
        g_B2[i] = __float2bfloat16(w);
    }
}

#define ROWB 80
#define TILEB (128 * ROWB)

// EmbW1 = embB @ W1T^T + b1 via HMMA. grid (16, 79), BM=128, BN=128, K=128 (verified R12).
__global__ __launch_bounds__(256) void embw1_mma(const float* __restrict__ b1) {
    __shared__ __align__(128) char smA[2][128 * ROWB];
    __shared__ __align__(128) char smB[2][128 * ROWB];

    const int tid = threadIdx.x;
    const int wid = tid >> 5, lane = tid & 31;
    const int warp_m = wid >> 2, warp_n = wid & 3;
    const int rowTile = blockIdx.y * 128, colTile = blockIdx.x * 128;

    const uint32_t sA0 = smem_u32(smA[0]), sA1 = smem_u32(smA[1]);
    const uint32_t sB0 = smem_u32(smB[0]), sB1 = smem_u32(smB[1]);

    const char* Agc = (const char*)g_embB;
    const char* Bgc = (const char*)g_W1T;
    const size_t strideBy = 256;

    int l_r[4], l_c[4];
    uint32_t l_so[4];
    size_t l_aoff[4], l_boff[4];
#pragma unroll
    for (int i = 0; i < 4; ++i) {
        int id = i * 256 + tid;
        int idx = id & 511;
        l_r[i] = idx >> 2; l_c[i] = idx & 3;
        l_so[i] = (uint32_t)(l_r[i] * ROWB + l_c[i] * 16);
        l_aoff[i] = (size_t)(rowTile + l_r[i]) * strideBy + l_c[i] * 16;
        l_boff[i] = (size_t)(colTile + l_r[i]) * strideBy + l_c[i] * 16;
    }

    float acc[4][4][4];
#pragma unroll
    for (int mi = 0; mi < 4; ++mi)
#pragma unroll
        for (int g = 0; g < 4; ++g)
#pragma unroll
            for (int j = 0; j < 4; ++j) acc[mi][g][j] = 0.0f;

    const int a_row = warp_m * 64 + (lane & 7) + ((lane >> 3) & 1) * 8;
    const int a_c16 = (lane >> 4) & 1;
    const int l15 = lane & 15;
    const int b_row = warp_n * 8 + (l15 & 7);
    const int b_c16 = l15 >> 3;

#pragma unroll
    for (int i = 0; i < 4; ++i) {
        int id = i * 256 + tid;
        if (id < 512) cp16(sA0 + l_so[i], Agc + l_aoff[i]);
        else          cp16(sB0 + l_so[i], Bgc + l_boff[i]);
    }
    CP_COMMIT();

    const int NT = 4;
    for (int kt = 0; kt < NT; ++kt) {
        int b = kt & 1;
        uint32_t sA = b ? sA1 : sA0;
        uint32_t sB = b ? sB1 : sB0;
        if (kt + 1 < NT) {
            uint32_t dA = b ? sA0 : sA1;
            uint32_t dB = b ? sB0 : sB1;
            size_t go = (size_t)(kt + 1) * 64;
#pragma unroll
            for (int i = 0; i < 4; ++i) {
                int id = i * 256 + tid;
                if (id < 512) cp16(dA + l_so[i], Agc + l_aoff[i] + go);
                else          cp16(dB + l_so[i], Bgc + l_boff[i] + go);
            }
            CP_COMMIT();
            asm volatile("cp.async.wait_group 1;");
        } else {
            asm volatile("cp.async.wait_group 0;");
        }
        __syncthreads();
#pragma unroll
        for (int ks = 0; ks < 2; ++ks) {
            uint32_t af[4][4], bf[4][2];
#pragma unroll
            for (int mi = 0; mi < 4; ++mi)
                ldmA(sA + (uint32_t)((a_row + mi * 16) * ROWB + ks * 32 + a_c16 * 16), af[mi]);
#pragma unroll
            for (int g = 0; g < 4; ++g)
                ldmB(sB + (uint32_t)((b_row + g * 32) * ROWB + ks * 32 + b_c16 * 16), bf[g]);
#pragma unroll
            for (int mi = 0; mi < 4; ++mi)
#pragma unroll
                for (int g = 0; g < 4; ++g)
                    mma16816(acc[mi][g], af[mi], bf[g]);
        }
        __syncthreads();
    }

#pragma unroll
    for (int mi = 0; mi < 4; ++mi) {
#pragma unroll
        for (int h = 0; h < 2; ++h) {
            int row = rowTile + warp_m * 64 + mi * 16 + (lane >> 2) + h * 8;
            if (row >= VOCAB) continue;
#pragma unroll
            for (int g = 0; g < 4; ++g) {
                int c = colTile + g * 32 + warp_n * 8 + (lane & 3) * 2;
                float2 bb = *(const float2*)(b1 + c);
                float2 o = make_float2(acc[mi][g][h * 2 + 0] + bb.x,
                                       acc[mi][g][h * 2 + 1] + bb.y);
                *(float2*)(g_EmbW1 + (size_t)row * ZDIM + c) = o;
            }
        }
    }
}

// ---------------- fused per-timestep kernel (3-stage pipeline, 1 sync/tile) ----------------
template<int KP, int LAYER>
__device__ __forceinline__ void step_body(
    const int* __restrict__ tokens, const float* __restrict__ b2, int t,
    const __nv_bfloat16* __restrict__ Ag, const __nv_bfloat16* __restrict__ Bg,
    float* __restrict__ Cst, __nv_bfloat16* __restrict__ d1, __nv_bfloat16* __restrict__ d2,
    int rowTile, int uTile, uint32_t sbA, uint32_t sbB,
    int tid, int warp_m, int warp_n, int lane)
{
    const size_t strideBy = (size_t)KP * 2;
    const char* Agc = (const char*)Ag;
    const char* Bgc = (const char*)Bg;

    int l_r[4], l_c[4];
    uint32_t l_so[4];
    size_t l_aoff[4], l_boff[4];
#pragma unroll
    for (int i = 0; i < 4; ++i) {
        int id = i * 256 + tid;
        int idx = id & 511;
        l_r[i] = idx >> 2; l_c[i] = idx & 3;
        l_so[i] = (uint32_t)(l_r[i] * ROWB + l_c[i] * 16);
        l_aoff[i] = (size_t)(rowTile + l_r[i]) * strideBy + l_c[i] * 16;
        int n = ((l_r[i] >> 5) * 512) + uTile + (l_r[i] & 31);
        l_boff[i] = (size_t)n * strideBy + l_c[i] * 16;
    }

#define ISSUE(ktv) do {                                                          \
        size_t go = (size_t)(ktv) * 64;                                          \
        uint32_t off = (uint32_t)((ktv) % 3) * TILEB;                            \
        _Pragma("unroll")                                                        \
        for (int i = 0; i < 4; ++i) {                                            \
            int id = i * 256 + tid;                                              \
            if (id < 512) cp16(sbA + off + l_so[i], Agc + l_aoff[i] + go);       \
            else          cp16(sbB + off + l_so[i], Bgc + l_boff[i] + go);       \
        }                                                                        \
        CP_COMMIT();                                                             \
    } while (0)

    float acc[4][4][4];
#pragma unroll
    for (int mi = 0; mi < 4; ++mi)
#pragma unroll
        for (int g = 0; g < 4; ++g)
#pragma unroll
            for (int j = 0; j < 4; ++j) acc[mi][g][j] = 0.0f;

    const int a_row = warp_m * 64 + (lane & 7) + ((lane >> 3) & 1) * 8;
    const int a_c16 = (lane >> 4) & 1;
    const int l15 = lane & 15;
    const int b_row = warp_n * 8 + (l15 & 7);
    const int b_c16 = l15 >> 3;
    const int u0 = uTile + warp_n * 8 + (lane & 3) * 2;

    const int NT = KP >> 5;

    ISSUE(0);
    ISSUE(1);

    for (int kt = 0; kt < NT; ++kt) {
        if (kt == NT - 1) asm volatile("cp.async.wait_group 0;");
        else              asm volatile("cp.async.wait_group 1;");   // tile kt retired
        __syncthreads();   // all warps done computing tile kt-1; buffer (kt+2)%3 free
        if (kt + 2 < NT) ISSUE(kt + 2);

        uint32_t sA = sbA + (uint32_t)(kt % 3) * TILEB;
        uint32_t sB = sbB + (uint32_t)(kt % 3) * TILEB;
#pragma unroll
        for (int ks = 0; ks < 2; ++ks) {
            uint32_t af[4][4], bf[4][2];
#pragma unroll
            for (int mi = 0; mi < 4; ++mi)
                ldmA(sA + (uint32_t)((a_row + mi * 16) * ROWB + ks * 32 + a_c16 * 16), af[mi]);
#pragma unroll
            for (int g = 0; g < 4; ++g)
                ldmB(sB + (uint32_t)((b_row + g * 32) * ROWB + ks * 32 + b_c16 * 16), bf[g]);
#pragma unroll
            for (int mi = 0; mi < 4; ++mi)
#pragma unroll
                for (int g = 0; g < 4; ++g)
                    mma16816(acc[mi][g], af[mi], bf[g]);
        }
    }
#undef ISSUE

    // epilogue (thread-local gates; layout verified R5/R6; MUFU fast transcendentals)
#pragma unroll
    for (int mi = 0; mi < 4; ++mi) {
#pragma unroll
        for (int h = 0; h < 2; ++h) {
            int row = rowTile + warp_m * 64 + mi * 16 + (lane >> 2) + h * 8;
            const float* Xrow;
            if (LAYER == 0) Xrow = g_EmbW1 + (size_t)tokens[row * SEQ + t] * ZDIM;
            else            Xrow = b2;
            float2 xz[4];
#pragma unroll
            for (int g = 0; g < 4; ++g) xz[g] = *(const float2*)(Xrow + g * 512 + u0);

            float zi0 = acc[mi][0][h * 2 + 0] + xz[0].x, zi1 = acc[mi][0][h * 2 + 1] + xz[0].y;
            float zf0 = acc[mi][1][h * 2 + 0] + xz[1].x, zf1 = acc[mi][1][h * 2 + 1] + xz[1].y;
            float zg0 = acc[mi][2][h * 2 + 0] + xz[2].x, zg1 = acc[mi][2][h * 2 + 1] + xz[2].y;
            float zo0 = acc[mi][3][h * 2 + 0] + xz[3].x, zo1 = acc[mi][3][h * 2 + 1] + xz[3].y;

            float* cp = Cst + (size_t)row * UNITS + u0;
            float2 c = *(float2*)cp;
            c.x = fsigm(zf0) * c.x + fsigm(zi0) * ftanh(zg0);
            c.y = fsigm(zf1) * c.y + fsigm(zi1) * ftanh(zg1);
            *(float2*)cp = c;
            float hv0 = fsigm(zo0) * ftanh(c.x);
            float hv1 = fsigm(zo1) * ftanh(c.y);

            __nv_bfloat16 bh0 = __float2bfloat16(hv0);
            __nv_bfloat16 bh1 = __float2bfloat16(hv1);
            uint32_t hiP = ((uint32_t)*(unsigned short*)&bh1 << 16) | *(unsigned short*)&bh0;

            if (LAYER == 0) {
                *(uint32_t*)(d1 + (size_t)row * K1 + u0) = hiP;          // h1 -> A1[a^1]
                *(uint32_t*)(d2 + (size_t)row * K2 + u0) = hiP;          // h1 -> A2[a].h1
            } else {
                *(uint32_t*)(d1 + (size_t)row * K2 + 512 + u0) = hiP;    // h2 -> A2[a^1].h2
                *(float2*)(g_H2f + (size_t)row * UNITS + u0) = make_float2(hv0, hv1);
            }
        }
    }
}

// launch tau runs layer1(t=tau) [y<8] and layer2(t=tau-1) [y>=8] concurrently (verified R12).
// __launch_bounds__(256, 2): guarantee 2 CTAs/SM -> whole 256-CTA grid co-resident in one wave,
// doubling warps/SMSP to hide LDSM latency + barrier skew (occ was 18.7%, tensor 22.8%).
__global__ __launch_bounds__(256, 2) void lstm_fused(const int* __restrict__ tokens,
                                                     const float* __restrict__ b2, int tau) {
    extern __shared__ __align__(128) char dynsm[];
    const uint32_t sbA = smem_u32(dynsm);
    const uint32_t sbB = sbA + 3 * TILEB;

    const int tid = threadIdx.x;
    const int wid = tid >> 5, lane = tid & 31;
    const int warp_m = wid >> 2, warp_n = wid & 3;
    const bool isL1 = blockIdx.y < 8;
    const int rowTile = (blockIdx.y & 7) * 128;
    const int uTile = blockIdx.x * 32;

    if (isL1) {
        if (tau >= SEQ) return;
        const int t = tau, a = t & 1;
        step_body<K1, 0>(tokens, b2, t, g_A1[a], g_B1, g_C1,
                         g_A1[a ^ 1], g_A2[a], rowTile, uTile, sbA, sbB,
                         tid, warp_m, warp_n, lane);
    } else {
        if (tau == 0) return;
        const int t = tau - 1, a = t & 1;
        step_body<K2, 1>(tokens, b2, t, g_A2[a], g_B2, g_C2,
                         g_A2[a ^ 1], nullptr, rowTile, uTile, sbA, sbB,
                         tid, warp_m, warp_n, lane);
    }
}

// ---------------- output head ----------------
__global__ void out_kernel(const float* __restrict__ Wout, const float* __restrict__ bout,
                           float* __restrict__ out) {
    int row = (blockIdx.x * blockDim.x + threadIdx.x) >> 5;
    int lane = threadIdx.x & 31;
    float s = 0.0f;
    for (int k = lane; k < UNITS; k += 32)
        s += g_H2f[(size_t)row * UNITS + k] * Wout[k];
#pragma unroll
    for (int off = 16; off; off >>= 1) s += __shfl_down_sync(0xffffffffu, s, off);
    if (lane == 0) out[row] = sigm(s + bout[0]);
}

// ---------------- launch ----------------
#define DYNSM (6 * TILEB)   // 61440 bytes: 3-stage A + B

extern "C" void kernel_launch(void* const* d_in, const int* in_sizes, int n_in,
                              void* d_out, int out_size) {
    const int*   tokens = (const int*)d_in[0];
    const float* emb    = (const float*)d_in[1];
    const float* W1     = (const float*)d_in[2];
    const float* U1     = (const float*)d_in[3];
    const float* b1     = (const float*)d_in[4];
    const float* W2     = (const float*)d_in[5];
    const float* U2     = (const float*)d_in[6];
    const float* b2     = (const float*)d_in[7];
    const float* Wout   = (const float*)d_in[8];
    const float* bout   = (const float*)d_in[9];
    float* out = (float*)d_out;

    static int smem_set = 0;
    if (!smem_set) {
        cudaFuncSetAttribute(lstm_fused, cudaFuncAttributeMaxDynamicSharedMemorySize, DYNSM);
        smem_set = 1;
    }

    prep_all<<<1024, 256>>>(emb, W1, U1, W2, U2);
    embw1_mma<<<dim3(16, VPAD / 128), 256>>>(b1);

    dim3 grid(16, 16);   // y<8: layer1 tiles, y>=8: layer2 tiles
    for (int tau = 0; tau <= SEQ; ++tau)
        lstm_fused<<<grid, 256, DYNSM>>>(tokens, b2, tau);

    out_kernel<<<BATCH / 8, 256>>>(Wout, bout, out);
}